// round 13
// baseline (speedup 1.0000x reference)
#include <cuda_runtime.h>
#include <cuda_fp16.h>
#include <cstdint>

// ---------------------------------------------------------------------------
// Banded causal attention (Longformer w=128, window 256, D=64) on mma.sync
// fp16 HMMA. QK: 3-product hi/lo split (Q pre-scaled by log2e). PV: 1 product.
// Mask+causal+max folded into QK epilogue. Whole compute body templated on the
// row-block index RB -> all loops compile-time, guard-free, pipelineable.
// blk0 handled via -inf additive mask (no special-case tiles).
// CTA = 128 q-rows, 8 warps, 1 CTA/SM; warp w owns row-block (w<4?w:11-w).
// ---------------------------------------------------------------------------

#define QHI 0u
#define QLO 18432u
#define KHI 36864u
#define KLO 73728u
#define VHI 110592u
#define AMS 147456u
#define SMEM_TOTAL 148480

#define LOG2E 1.4426950408889634f

static __device__ __forceinline__ uint32_t smem_u32(const void* p) {
    uint32_t a;
    asm("{ .reg .u64 t; cvta.to.shared.u64 t, %1; cvt.u32.u64 %0, t; }"
        : "=r"(a) : "l"(p));
    return a;
}
// pack two f32 -> f16x2 (first arg in low half)
static __device__ __forceinline__ uint32_t packh(float lo, float hi) {
    uint32_t r;
    asm("cvt.rn.f16x2.f32 %0, %1, %2;" : "=r"(r) : "f"(hi), "f"(lo));
    return r;
}
static __device__ __forceinline__ float lowf(uint32_t u) {
    return __half2float(__ushort_as_half((unsigned short)(u & 0xffffu)));
}
static __device__ __forceinline__ float highf(uint32_t u) {
    return __half2float(__ushort_as_half((unsigned short)(u >> 16)));
}
static __device__ __forceinline__ float ex2f(float x) {
    float y;
    asm("ex2.approx.ftz.f32 %0, %1;" : "=f"(y) : "f"(x));
    return y;
}
static __device__ __forceinline__ void ldsm4(uint32_t r[4], uint32_t a) {
    asm volatile("ldmatrix.sync.aligned.m8n8.x4.shared.b16 {%0,%1,%2,%3}, [%4];"
                 : "=r"(r[0]), "=r"(r[1]), "=r"(r[2]), "=r"(r[3]) : "r"(a));
}
static __device__ __forceinline__ void ldsm4t(uint32_t r[4], uint32_t a) {
    asm volatile("ldmatrix.sync.aligned.m8n8.x4.trans.shared.b16 {%0,%1,%2,%3}, [%4];"
                 : "=r"(r[0]), "=r"(r[1]), "=r"(r[2]), "=r"(r[3]) : "r"(a));
}
static __device__ __forceinline__ void mma(float d[4], const uint32_t a[4],
                                           uint32_t b0, uint32_t b1) {
    asm volatile(
        "mma.sync.aligned.m16n8k16.row.col.f32.f16.f16.f32 "
        "{%0,%1,%2,%3}, {%4,%5,%6,%7}, {%8,%9}, {%0,%1,%2,%3};"
        : "+f"(d[0]), "+f"(d[1]), "+f"(d[2]), "+f"(d[3])
        : "r"(a[0]), "r"(a[1]), "r"(a[2]), "r"(a[3]), "r"(b0), "r"(b1));
}
// split float4 -> two f16x2 hi + two f16x2 lo
static __device__ __forceinline__ void split4(float4 v, uint32_t& h0, uint32_t& h1,
                                              uint32_t& l0, uint32_t& l1) {
    h0 = packh(v.x, v.y);
    h1 = packh(v.z, v.w);
    l0 = packh(v.x - lowf(h0), v.y - highf(h0));
    l1 = packh(v.z - lowf(h1), v.w - highf(h1));
}

// Whole per-warp compute body, fully unrolled for compile-time RB.
template <int RB>
static __device__ __forceinline__ void qk_softmax_pv(
    const char* __restrict__ sm, uint32_t kb_h, uint32_t kb_l, uint32_t vb_h,
    const uint32_t aqh[4][4], const uint32_t aql[4][4],
    int tg, int r0, float* __restrict__ Ob)
{
    constexpr int NE = 18 + 2 * RB;   // n-tiles (exclusive causal bound)
    constexpr int NP = NE / 2;        // tile pairs; last pair is boundary
    const float* AMsm = reinterpret_cast<const float*>(sm + AMS);
    const int lim0 = 128 + r0, lim1 = lim0 + 8;

    union { float s[NE][4]; uint32_t u[NE][4]; } P;
    float m0 = -1e30f, m1 = -1e30f;

    // ---- Phase A: S = Q K^T (3-product fp16 split), guard-free ----
#pragma unroll
    for (int i = 0; i < NP; ++i) {
        const int nt = 2 * i;
        float dA0[4] = {0,0,0,0}, dB0[4] = {0,0,0,0};
        float dA1[4] = {0,0,0,0}, dB1[4] = {0,0,0,0};
#pragma unroll
        for (int p = 0; p < 2; ++p) {
            uint32_t bh[4], bl[4], ch[4], cl[4];
            ldsm4(bh, kb_h + (uint32_t)nt * 8u * 144u + p * 64);
            ldsm4(bl, kb_l + (uint32_t)nt * 8u * 144u + p * 64);
            ldsm4(ch, kb_h + (uint32_t)(nt + 1) * 8u * 144u + p * 64);
            ldsm4(cl, kb_l + (uint32_t)(nt + 1) * 8u * 144u + p * 64);
            const int k0 = 2 * p, k1 = 2 * p + 1;
            mma(dA0, aqh[k0], bh[0], bh[1]);
            mma(dA1, aqh[k0], ch[0], ch[1]);
            mma(dB0, aqh[k0], bl[0], bl[1]);
            mma(dB1, aqh[k0], cl[0], cl[1]);
            mma(dA0, aqh[k1], bh[2], bh[3]);
            mma(dA1, aqh[k1], ch[2], ch[3]);
            mma(dB0, aqh[k1], bl[2], bl[3]);
            mma(dB1, aqh[k1], cl[2], cl[3]);
            if (p == 0) {
                mma(dA0, aql[k0], bh[0], bh[1]);
                mma(dA1, aql[k0], ch[0], ch[1]);
                mma(dA0, aql[k1], bh[2], bh[3]);
                mma(dA1, aql[k1], ch[2], ch[3]);
            } else {
                mma(dB0, aql[k0], bh[0], bh[1]);
                mma(dB1, aql[k0], ch[0], ch[1]);
                mma(dB0, aql[k1], bh[2], bh[3]);
                mma(dB1, aql[k1], ch[2], ch[3]);
            }
        }
        // epilogue: mask fold + causal (last pair only) + running max
        int col0 = nt * 8 + 2 * tg;
        float am0 = AMsm[col0],     am1 = AMsm[col0 + 1];
        float bm0 = AMsm[col0 + 8], bm1 = AMsm[col0 + 9];
        if (i < NP - 1) {              // interior pair (compile-time branch)
            float v0 = dA0[0] + dB0[0] + am0;
            float v1 = dA0[1] + dB0[1] + am1;
            float v2 = dA0[2] + dB0[2] + am0;
            float v3 = dA0[3] + dB0[3] + am1;
            float u0 = dA1[0] + dB1[0] + bm0;
            float u1 = dA1[1] + dB1[1] + bm1;
            float u2 = dA1[2] + dB1[2] + bm0;
            float u3 = dA1[3] + dB1[3] + bm1;
            P.s[nt][0] = v0; P.s[nt][1] = v1; P.s[nt][2] = v2; P.s[nt][3] = v3;
            P.s[nt+1][0] = u0; P.s[nt+1][1] = u1; P.s[nt+1][2] = u2; P.s[nt+1][3] = u3;
            m0 = fmaxf(m0, fmaxf(fmaxf(v0, v1), fmaxf(u0, u1)));
            m1 = fmaxf(m1, fmaxf(fmaxf(v2, v3), fmaxf(u2, u3)));
        } else {                       // boundary pair: causal predication
            int c1 = col0 + 1, c8 = col0 + 8, c9 = col0 + 9;
            float v0 = (col0 <= lim0) ? dA0[0] + dB0[0] + am0 : -1e30f;
            float v1 = (c1   <= lim0) ? dA0[1] + dB0[1] + am1 : -1e30f;
            float v2 = (col0 <= lim1) ? dA0[2] + dB0[2] + am0 : -1e30f;
            float v3 = (c1   <= lim1) ? dA0[3] + dB0[3] + am1 : -1e30f;
            float u0 = (c8   <= lim0) ? dA1[0] + dB1[0] + bm0 : -1e30f;
            float u1 = (c9   <= lim0) ? dA1[1] + dB1[1] + bm1 : -1e30f;
            float u2 = (c8   <= lim1) ? dA1[2] + dB1[2] + bm0 : -1e30f;
            float u3 = (c9   <= lim1) ? dA1[3] + dB1[3] + bm1 : -1e30f;
            P.s[nt][0] = v0; P.s[nt][1] = v1; P.s[nt][2] = v2; P.s[nt][3] = v3;
            P.s[nt+1][0] = u0; P.s[nt+1][1] = u1; P.s[nt+1][2] = u2; P.s[nt+1][3] = u3;
            m0 = fmaxf(m0, fmaxf(fmaxf(v0, v1), fmaxf(u0, u1)));
            m1 = fmaxf(m1, fmaxf(fmaxf(v2, v3), fmaxf(u2, u3)));
        }
    }

    // ---- finish max across the quad ----
    m0 = fmaxf(m0, __shfl_xor_sync(0xffffffffu, m0, 1));
    m0 = fmaxf(m0, __shfl_xor_sync(0xffffffffu, m0, 2));
    m1 = fmaxf(m1, __shfl_xor_sync(0xffffffffu, m1, 1));
    m1 = fmaxf(m1, __shfl_xor_sync(0xffffffffu, m1, 2));

    // ---- single softmax pass: exp + sum + pack ----
    float s0 = 0.f, s1 = 0.f;
#pragma unroll
    for (int nt = 0; nt < NE; ++nt) {
        float e0 = ex2f(P.s[nt][0] - m0);
        float e1 = ex2f(P.s[nt][1] - m0);
        float e2 = ex2f(P.s[nt][2] - m1);
        float e3 = ex2f(P.s[nt][3] - m1);
        s0 += e0 + e1; s1 += e2 + e3;
        P.u[nt][0] = packh(e0, e1);     // unnormalized fp16 P
        P.u[nt][1] = packh(e2, e3);
    }
    s0 += __shfl_xor_sync(0xffffffffu, s0, 1);
    s0 += __shfl_xor_sync(0xffffffffu, s0, 2);
    s1 += __shfl_xor_sync(0xffffffffu, s1, 1);
    s1 += __shfl_xor_sync(0xffffffffu, s1, 2);
    const float inv0 = __frcp_rn(s0);
    const float inv1 = __frcp_rn(s1);

    // ---- Phase B: O = P V (single product), guard-free ----
    float o[8][4];
#pragma unroll
    for (int i = 0; i < 8; ++i) { o[i][0] = o[i][1] = o[i][2] = o[i][3] = 0.f; }

#pragma unroll
    for (int kt = 0; kt < NP; ++kt) {
        uint32_t ah[4] = {P.u[2*kt][0], P.u[2*kt][1], P.u[2*kt+1][0], P.u[2*kt+1][1]};
#pragma unroll
        for (int dp = 0; dp < 4; ++dp) {
            uint32_t bh[4];
            ldsm4t(bh, vb_h + (uint32_t)kt * 16u * 144u + dp * 32);
            mma(o[2*dp],     ah, bh[0], bh[1]);
            mma(o[2*dp + 1], ah, bh[2], bh[3]);
        }
    }

    // ---- store O (normalize here) ----
#pragma unroll
    for (int dp = 0; dp < 8; ++dp) {
        int d = dp * 8 + 2 * tg;
        *reinterpret_cast<float2*>(Ob + d) =
            make_float2(o[dp][0] * inv0, o[dp][1] * inv0);
        *reinterpret_cast<float2*>(Ob + 8 * 64 + d) =
            make_float2(o[dp][2] * inv1, o[dp][3] * inv1);
    }
}

__global__ __launch_bounds__(256)
void lf_hmma_kernel(const float* __restrict__ Q, const float* __restrict__ K,
                    const float* __restrict__ V, const float* __restrict__ AM,
                    float* __restrict__ O, int S) {
    extern __shared__ char sm[];
    const uint32_t sb = smem_u32(sm);
    const int tid  = threadIdx.x;
    const int w    = tid >> 5;
    const int lane = tid & 31;
    const int g    = lane >> 2;
    const int tg   = lane & 3;
    const int rb   = (w < 4) ? w : 11 - w;   // row-block: SMSP-balanced map
    const int h    = blockIdx.y;
    const int q0   = blockIdx.x << 7;
    const int kb   = q0 - 128;
    const bool blk0 = (q0 == 0);

    const float* Qg = Q + ((size_t)h * S + q0) * 64;
    const float* Kg = K + (size_t)h * S * 64;
    const float* Vg = V + (size_t)h * S * 64;

    // ---- stage Q*log2e (hi/lo), K (hi/lo), V (hi only) + mask*log2e ----
#pragma unroll
    for (int it = 0; it < 8; ++it) {
        int idx = it * 256 + tid, row = idx >> 4, c4 = idx & 15;
        float4 q = *reinterpret_cast<const float4*>(Qg + row * 64 + c4 * 4);
        q.x *= LOG2E; q.y *= LOG2E; q.z *= LOG2E; q.w *= LOG2E;
        uint32_t h0, h1, l0, l1; split4(q, h0, h1, l0, l1);
        uint32_t off = (uint32_t)row * 144u + (uint32_t)c4 * 8u;
        *reinterpret_cast<uint2*>(sm + QHI + off) = make_uint2(h0, h1);
        *reinterpret_cast<uint2*>(sm + QLO + off) = make_uint2(l0, l1);
    }
#pragma unroll
    for (int it = 0; it < 16; ++it) {
        int idx = it * 256 + tid, y = idx >> 4, c4 = idx & 15;
        float4 kv = make_float4(0.f, 0.f, 0.f, 0.f);
        float4 vv = make_float4(0.f, 0.f, 0.f, 0.f);
        if (!blk0 || y >= 128) {
            kv = *reinterpret_cast<const float4*>(Kg + (size_t)(kb + y) * 64 + c4 * 4);
            vv = *reinterpret_cast<const float4*>(Vg + (size_t)(kb + y) * 64 + c4 * 4);
        }
        uint32_t off = (uint32_t)y * 144u + (uint32_t)c4 * 8u;
        uint32_t h0, h1, l0, l1; split4(kv, h0, h1, l0, l1);
        *reinterpret_cast<uint2*>(sm + KHI + off) = make_uint2(h0, h1);
        *reinterpret_cast<uint2*>(sm + KLO + off) = make_uint2(l0, l1);
        h0 = packh(vv.x, vv.y); h1 = packh(vv.z, vv.w);
        *reinterpret_cast<uint2*>(sm + VHI + off) = make_uint2(h0, h1);
    }
    {
        // blk0: out-of-range keys get -inf mask -> exp2 == 0, uniform code path
        float am = (blk0 && tid < 128) ? -1e30f : AM[kb + tid] * LOG2E;
        reinterpret_cast<float*>(sm + AMS)[tid] = am;
    }
    __syncthreads();

    // ---- A fragments for Q (4 k-steps, hi+lo) ----
    uint32_t aqh[4][4], aql[4][4];
    {
        uint32_t ab = sb + QHI + (uint32_t)(rb * 16 + (lane & 15)) * 144u +
                      (uint32_t)((lane >> 4) & 1) * 16u;
#pragma unroll
        for (int ks = 0; ks < 4; ++ks) {
            ldsm4(aqh[ks], ab + ks * 32);
            ldsm4(aql[ks], ab + (QLO - QHI) + ks * 32);
        }
    }

    const uint32_t kb_h = sb + KHI + (uint32_t)(lane & 7) * 144u +
                          (uint32_t)((lane >> 3) & 3) * 16u;
    const uint32_t kb_l = kb_h + (KLO - KHI);
    const uint32_t vb_h = sb + VHI +
        (uint32_t)(((lane >> 3) & 1) * 8 + (lane & 7)) * 144u +
        (uint32_t)((lane >> 4) & 1) * 16u;
    const int r0 = rb * 16 + g;
    float* Ob = O + ((size_t)h * S + q0 + r0) * 64;

    switch (rb) {
        case 0: qk_softmax_pv<0>(sm, kb_h, kb_l, vb_h, aqh, aql, tg, r0, Ob); break;
        case 1: qk_softmax_pv<1>(sm, kb_h, kb_l, vb_h, aqh, aql, tg, r0, Ob); break;
        case 2: qk_softmax_pv<2>(sm, kb_h, kb_l, vb_h, aqh, aql, tg, r0, Ob); break;
        case 3: qk_softmax_pv<3>(sm, kb_h, kb_l, vb_h, aqh, aql, tg, r0, Ob); break;
        case 4: qk_softmax_pv<4>(sm, kb_h, kb_l, vb_h, aqh, aql, tg, r0, Ob); break;
        case 5: qk_softmax_pv<5>(sm, kb_h, kb_l, vb_h, aqh, aql, tg, r0, Ob); break;
        case 6: qk_softmax_pv<6>(sm, kb_h, kb_l, vb_h, aqh, aql, tg, r0, Ob); break;
        default: qk_softmax_pv<7>(sm, kb_h, kb_l, vb_h, aqh, aql, tg, r0, Ob); break;
    }
}

extern "C" void kernel_launch(void* const* d_in, const int* in_sizes, int n_in,
                              void* d_out, int out_size) {
    const float* Q  = (const float*)d_in[0];
    const float* K  = (const float*)d_in[1];
    const float* V  = (const float*)d_in[2];
    const float* AM = (const float*)d_in[3];
    float* O = (float*)d_out;

    const int S  = in_sizes[3];
    const int BH = in_sizes[0] / (S * 64);

    cudaFuncSetAttribute(lf_hmma_kernel,
                         cudaFuncAttributeMaxDynamicSharedMemorySize, SMEM_TOTAL);

    dim3 grid(S / 128, BH);
    lf_hmma_kernel<<<grid, 256, SMEM_TOTAL>>>(Q, K, V, AM, O, S);
}

// round 14
// speedup vs baseline: 2.5081x; 2.5081x over previous
#include <cuda_runtime.h>
#include <cuda_fp16.h>
#include <cstdint>

// ---------------------------------------------------------------------------
// Banded causal attention (Longformer w=128, window 256, D=64) on mma.sync
// fp16 HMMA, flash-online softmax: QK pair -> quad max -> rescale o -> exp
// -> PV, all fused per tile-pair (no persistent score array).
// Q loaded directly to fragments from global (no Q smem). K hi/lo + V in smem.
// CTA = 128 q-rows, 8 warps; 2 CTAs/SM (smem 109KB, target <=128 regs).
// ---------------------------------------------------------------------------

#define KHI 0u
#define KLO 36864u
#define VHI 73728u
#define AMS 110592u
#define SMEM_TOTAL 111616

#define LOG2E 1.4426950408889634f

static __device__ __forceinline__ uint32_t smem_u32(const void* p) {
    uint32_t a;
    asm("{ .reg .u64 t; cvta.to.shared.u64 t, %1; cvt.u32.u64 %0, t; }"
        : "=r"(a) : "l"(p));
    return a;
}
// pack two f32 -> f16x2 (first arg in low half)
static __device__ __forceinline__ uint32_t packh(float lo, float hi) {
    uint32_t r;
    asm("cvt.rn.f16x2.f32 %0, %1, %2;" : "=r"(r) : "f"(hi), "f"(lo));
    return r;
}
static __device__ __forceinline__ float lowf(uint32_t u) {
    return __half2float(__ushort_as_half((unsigned short)(u & 0xffffu)));
}
static __device__ __forceinline__ float highf(uint32_t u) {
    return __half2float(__ushort_as_half((unsigned short)(u >> 16)));
}
static __device__ __forceinline__ float ex2f(float x) {
    float y;
    asm("ex2.approx.ftz.f32 %0, %1;" : "=f"(y) : "f"(x));
    return y;
}
static __device__ __forceinline__ void ldsm4(uint32_t r[4], uint32_t a) {
    asm volatile("ldmatrix.sync.aligned.m8n8.x4.shared.b16 {%0,%1,%2,%3}, [%4];"
                 : "=r"(r[0]), "=r"(r[1]), "=r"(r[2]), "=r"(r[3]) : "r"(a));
}
static __device__ __forceinline__ void ldsm4t(uint32_t r[4], uint32_t a) {
    asm volatile("ldmatrix.sync.aligned.m8n8.x4.trans.shared.b16 {%0,%1,%2,%3}, [%4];"
                 : "=r"(r[0]), "=r"(r[1]), "=r"(r[2]), "=r"(r[3]) : "r"(a));
}
static __device__ __forceinline__ void mma(float d[4], const uint32_t a[4],
                                           uint32_t b0, uint32_t b1) {
    asm volatile(
        "mma.sync.aligned.m16n8k16.row.col.f32.f16.f16.f32 "
        "{%0,%1,%2,%3}, {%4,%5,%6,%7}, {%8,%9}, {%0,%1,%2,%3};"
        : "+f"(d[0]), "+f"(d[1]), "+f"(d[2]), "+f"(d[3])
        : "r"(a[0]), "r"(a[1]), "r"(a[2]), "r"(a[3]), "r"(b0), "r"(b1));
}
// split float4 -> two f16x2 hi + two f16x2 lo
static __device__ __forceinline__ void split4(float4 v, uint32_t& h0, uint32_t& h1,
                                              uint32_t& l0, uint32_t& l1) {
    h0 = packh(v.x, v.y);
    h1 = packh(v.z, v.w);
    l0 = packh(v.x - lowf(h0), v.y - highf(h0));
    l1 = packh(v.z - lowf(h1), v.w - highf(h1));
}
// scale float2 by LOG2E, split to f16x2 hi + lo
static __device__ __forceinline__ void split2s(float2 v, uint32_t& h, uint32_t& l) {
    float x = v.x * LOG2E, y = v.y * LOG2E;
    h = packh(x, y);
    l = packh(x - lowf(h), y - highf(h));
}

__global__ __launch_bounds__(256, 2)
void lf_hmma_kernel(const float* __restrict__ Q, const float* __restrict__ K,
                    const float* __restrict__ V, const float* __restrict__ AM,
                    float* __restrict__ O, int S) {
    extern __shared__ char sm[];
    const uint32_t sb = smem_u32(sm);
    const int tid  = threadIdx.x;
    const int w    = tid >> 5;
    const int lane = tid & 31;
    const int g    = lane >> 2;
    const int tg   = lane & 3;
    const int rb   = (w < 4) ? w : 11 - w;   // row-block: SMSP-balanced map
    const int h    = blockIdx.y;
    const int q0   = blockIdx.x << 7;
    const int kb   = q0 - 128;
    const bool blk0 = (q0 == 0);

    const float* Qg = Q + ((size_t)h * S + q0) * 64;
    const float* Kg = K + (size_t)h * S * 64;
    const float* Vg = V + (size_t)h * S * 64;

    // ---- stage K (hi/lo) and V (hi) + mask*log2e into smem ----
#pragma unroll
    for (int it = 0; it < 16; ++it) {
        int idx = it * 256 + tid, y = idx >> 4, c4 = idx & 15;
        float4 kv = make_float4(0.f, 0.f, 0.f, 0.f);
        float4 vv = make_float4(0.f, 0.f, 0.f, 0.f);
        if (!blk0 || y >= 128) {
            kv = *reinterpret_cast<const float4*>(Kg + (size_t)(kb + y) * 64 + c4 * 4);
            vv = *reinterpret_cast<const float4*>(Vg + (size_t)(kb + y) * 64 + c4 * 4);
        }
        uint32_t off = (uint32_t)y * 144u + (uint32_t)c4 * 8u;
        uint32_t h0, h1, l0, l1; split4(kv, h0, h1, l0, l1);
        *reinterpret_cast<uint2*>(sm + KHI + off) = make_uint2(h0, h1);
        *reinterpret_cast<uint2*>(sm + KLO + off) = make_uint2(l0, l1);
        h0 = packh(vv.x, vv.y); h1 = packh(vv.z, vv.w);
        *reinterpret_cast<uint2*>(sm + VHI + off) = make_uint2(h0, h1);
    }
    {
        float am = 0.f;
        if (!blk0 || tid >= 128) am = AM[kb + tid] * LOG2E;
        reinterpret_cast<float*>(sm + AMS)[tid] = am;
    }

    // ---- Q fragments direct from global (scaled by log2e, hi/lo split) ----
    const int r0 = rb * 16 + g;
    uint32_t aqh[4][4], aql[4][4];
    {
        const float* Qr0 = Qg + (size_t)r0 * 64 + 2 * tg;
        const float* Qr8 = Qr0 + 8 * 64;
#pragma unroll
        for (int ks = 0; ks < 4; ++ks) {
            float2 q00 = *reinterpret_cast<const float2*>(Qr0 + 16 * ks);
            float2 q10 = *reinterpret_cast<const float2*>(Qr8 + 16 * ks);
            float2 q08 = *reinterpret_cast<const float2*>(Qr0 + 16 * ks + 8);
            float2 q18 = *reinterpret_cast<const float2*>(Qr8 + 16 * ks + 8);
            split2s(q00, aqh[ks][0], aql[ks][0]);
            split2s(q10, aqh[ks][1], aql[ks][1]);
            split2s(q08, aqh[ks][2], aql[ks][2]);
            split2s(q18, aqh[ks][3], aql[ks][3]);
        }
    }
    __syncthreads();

    const int ns  = blk0 ? 16 : 0;
    const int ne  = 18 + 2 * rb;   // exclusive n-tile bound (causal)
    const int ntb = 16 + 2 * rb;   // first boundary n-tile

    const int lim0 = 128 + r0, lim1 = lim0 + 8;
    const float* AMsm = reinterpret_cast<const float*>(sm + AMS);

    const uint32_t kb_h = sb + KHI + (uint32_t)(lane & 7) * 144u +
                          (uint32_t)((lane >> 3) & 3) * 16u;
    const uint32_t kb_l = kb_h + (KLO - KHI);
    const uint32_t vb_h = sb + VHI +
        (uint32_t)(((lane >> 3) & 1) * 8 + (lane & 7)) * 144u +
        (uint32_t)((lane >> 4) & 1) * 16u;

    float m0 = -1e30f, m1 = -1e30f;
    float s0 = 0.f, s1 = 0.f;
    float o[8][4];
#pragma unroll
    for (int i = 0; i < 8; ++i) { o[i][0] = o[i][1] = o[i][2] = o[i][3] = 0.f; }

    // ---- fused flash loop over tile pairs: QK -> online softmax -> PV ----
#pragma unroll
    for (int nt = 0; nt < 32; nt += 2) {
        if (nt < ns || nt >= ne) continue;
        float dA0[4] = {0,0,0,0}, dB0[4] = {0,0,0,0};
        float dA1[4] = {0,0,0,0}, dB1[4] = {0,0,0,0};
#pragma unroll
        for (int p = 0; p < 2; ++p) {
            uint32_t bh[4], bl[4], ch[4], cl[4];
            ldsm4(bh, kb_h + (uint32_t)nt * 8u * 144u + p * 64);
            ldsm4(bl, kb_l + (uint32_t)nt * 8u * 144u + p * 64);
            ldsm4(ch, kb_h + (uint32_t)(nt + 1) * 8u * 144u + p * 64);
            ldsm4(cl, kb_l + (uint32_t)(nt + 1) * 8u * 144u + p * 64);
            const int k0 = 2 * p, k1 = 2 * p + 1;
            mma(dA0, aqh[k0], bh[0], bh[1]);
            mma(dA1, aqh[k0], ch[0], ch[1]);
            mma(dB0, aqh[k0], bl[0], bl[1]);
            mma(dB1, aqh[k0], cl[0], cl[1]);
            mma(dA0, aqh[k1], bh[2], bh[3]);
            mma(dA1, aqh[k1], ch[2], ch[3]);
            mma(dB0, aqh[k1], bl[2], bl[3]);
            mma(dB1, aqh[k1], cl[2], cl[3]);
            if (p == 0) {
                mma(dA0, aql[k0], bh[0], bh[1]);
                mma(dA1, aql[k0], ch[0], ch[1]);
                mma(dA0, aql[k1], bh[2], bh[3]);
                mma(dA1, aql[k1], ch[2], ch[3]);
            } else {
                mma(dB0, aql[k0], bh[0], bh[1]);
                mma(dB1, aql[k0], ch[0], ch[1]);
                mma(dB0, aql[k1], bh[2], bh[3]);
                mma(dB1, aql[k1], ch[2], ch[3]);
            }
        }
        // ---- epilogue: mask fold (+ causal on boundary pairs) ----
        int col0 = nt * 8 + 2 * tg;
        float am0 = AMsm[col0],     am1 = AMsm[col0 + 1];
        float bm0 = AMsm[col0 + 8], bm1 = AMsm[col0 + 9];
        float v0, v1, v2, v3, u0, u1, u2, u3;
        if (nt < ntb) {
            v0 = dA0[0] + dB0[0] + am0;
            v1 = dA0[1] + dB0[1] + am1;
            v2 = dA0[2] + dB0[2] + am0;
            v3 = dA0[3] + dB0[3] + am1;
            u0 = dA1[0] + dB1[0] + bm0;
            u1 = dA1[1] + dB1[1] + bm1;
            u2 = dA1[2] + dB1[2] + bm0;
            u3 = dA1[3] + dB1[3] + bm1;
        } else {
            int c1 = col0 + 1, c8 = col0 + 8, c9 = col0 + 9;
            v0 = (col0 <= lim0) ? dA0[0] + dB0[0] + am0 : -1e30f;
            v1 = (c1   <= lim0) ? dA0[1] + dB0[1] + am1 : -1e30f;
            v2 = (col0 <= lim1) ? dA0[2] + dB0[2] + am0 : -1e30f;
            v3 = (c1   <= lim1) ? dA0[3] + dB0[3] + am1 : -1e30f;
            u0 = (c8   <= lim0) ? dA1[0] + dB1[0] + bm0 : -1e30f;
            u1 = (c9   <= lim0) ? dA1[1] + dB1[1] + bm1 : -1e30f;
            u2 = (c8   <= lim1) ? dA1[2] + dB1[2] + bm0 : -1e30f;
            u3 = (c9   <= lim1) ? dA1[3] + dB1[3] + bm1 : -1e30f;
        }
        // ---- online max (quad-wide) + rescale ----
        float pm0 = fmaxf(fmaxf(v0, v1), fmaxf(u0, u1));
        float pm1 = fmaxf(fmaxf(v2, v3), fmaxf(u2, u3));
        pm0 = fmaxf(pm0, __shfl_xor_sync(0xffffffffu, pm0, 1));
        pm0 = fmaxf(pm0, __shfl_xor_sync(0xffffffffu, pm0, 2));
        pm1 = fmaxf(pm1, __shfl_xor_sync(0xffffffffu, pm1, 1));
        pm1 = fmaxf(pm1, __shfl_xor_sync(0xffffffffu, pm1, 2));
        float n0 = fmaxf(m0, pm0), n1 = fmaxf(m1, pm1);
        float rs0 = ex2f(m0 - n0), rs1 = ex2f(m1 - n1);
        m0 = n0; m1 = n1;
        s0 *= rs0; s1 *= rs1;
#pragma unroll
        for (int i = 0; i < 8; ++i) {
            o[i][0] *= rs0; o[i][1] *= rs0;
            o[i][2] *= rs1; o[i][3] *= rs1;
        }
        // ---- exp + sum + pack ----
        float e0 = ex2f(v0 - m0), e1 = ex2f(v1 - m0);
        float e2 = ex2f(v2 - m1), e3 = ex2f(v3 - m1);
        float f0 = ex2f(u0 - m0), f1 = ex2f(u1 - m0);
        float f2 = ex2f(u2 - m1), f3 = ex2f(u3 - m1);
        s0 += (e0 + e1) + (f0 + f1);
        s1 += (e2 + e3) + (f2 + f3);
        uint32_t ah[4];
        ah[0] = packh(e0, e1);
        ah[1] = packh(e2, e3);
        ah[2] = packh(f0, f1);
        ah[3] = packh(f2, f3);
        // ---- PV for this k-tile ----
        const int kt = nt >> 1;
#pragma unroll
        for (int dp = 0; dp < 4; ++dp) {
            uint32_t bh[4];
            ldsm4t(bh, vb_h + (uint32_t)kt * 16u * 144u + dp * 32);
            mma(o[2*dp],     ah, bh[0], bh[1]);
            mma(o[2*dp + 1], ah, bh[2], bh[3]);
        }
    }

    // ---- final sums across quad, normalize, store ----
    s0 += __shfl_xor_sync(0xffffffffu, s0, 1);
    s0 += __shfl_xor_sync(0xffffffffu, s0, 2);
    s1 += __shfl_xor_sync(0xffffffffu, s1, 1);
    s1 += __shfl_xor_sync(0xffffffffu, s1, 2);
    const float inv0 = __frcp_rn(s0);
    const float inv1 = __frcp_rn(s1);

    float* Ob = O + ((size_t)h * S + q0 + r0) * 64;
#pragma unroll
    for (int dp = 0; dp < 8; ++dp) {
        int d = dp * 8 + 2 * tg;
        *reinterpret_cast<float2*>(Ob + d) =
            make_float2(o[dp][0] * inv0, o[dp][1] * inv0);
        *reinterpret_cast<float2*>(Ob + 8 * 64 + d) =
            make_float2(o[dp][2] * inv1, o[dp][3] * inv1);
    }
}

extern "C" void kernel_launch(void* const* d_in, const int* in_sizes, int n_in,
                              void* d_out, int out_size) {
    const float* Q  = (const float*)d_in[0];
    const float* K  = (const float*)d_in[1];
    const float* V  = (const float*)d_in[2];
    const float* AM = (const float*)d_in[3];
    float* O = (float*)d_out;

    const int S  = in_sizes[3];
    const int BH = in_sizes[0] / (S * 64);

    cudaFuncSetAttribute(lf_hmma_kernel,
                         cudaFuncAttributeMaxDynamicSharedMemorySize, SMEM_TOTAL);

    dim3 grid(S / 128, BH);
    lf_hmma_kernel<<<grid, 256, SMEM_TOTAL>>>(Q, K, V, AM, O, S);
}